// round 15
// baseline (speedup 1.0000x reference)
#include <cuda_runtime.h>
#include <math.h>
#include <stdint.h>

#define NUM_SEQS   64
#define NUM_HEADS  32
#define KVH        8
#define GQ         4      // query heads per kv head
#define HD         128    // head size
#define BS         16     // paged block size
#define MAXL       2048
#define MAXB       128    // max blocks per seq
#define PART       256    // tokens per split-KV partition
#define NP         (MAXL / PART)   // 8
#define CH         32     // tokens per pipeline chunk = 2 paged blocks
#define NTHREADS   512
#define NWARPS     16
#define FULLMASK   0xffffffffu

// Split-KV scratch (device globals)
__device__ float g_pacc[NUM_SEQS * KVH * NP * GQ * HD];
__device__ float g_pl[NUM_SEQS * KVH * NP * GQ];
__device__ int   g_cnt[NUM_SEQS * KVH];    // zero-initialized; self-cleaning

// ---- packed f32x2 helpers ----
__device__ __forceinline__ uint64_t pack2(float lo, float hi) {
    uint64_t r; asm("mov.b64 %0, {%1, %2};" : "=l"(r) : "f"(lo), "f"(hi)); return r;
}
__device__ __forceinline__ void unpack2(float& lo, float& hi, uint64_t v) {
    asm("mov.b64 {%0, %1}, %2;" : "=f"(lo), "=f"(hi) : "l"(v));
}
__device__ __forceinline__ uint64_t fma2(uint64_t a, uint64_t b, uint64_t c) {
    uint64_t d;
    asm("fma.rn.f32x2 %0, %1, %2, %3;" : "=l"(d) : "l"(a), "l"(b), "l"(c));
    return d;
}
__device__ __forceinline__ uint64_t mul2(uint64_t a, uint64_t b) {
    uint64_t d;
    asm("mul.rn.f32x2 %0, %1, %2;" : "=l"(d) : "l"(a), "l"(b));
    return d;
}

struct AccState {
    uint64_t a0lo, a0hi, a1lo, a1hi, a2lo, a2hi, a3lo, a3hi;
    float    lsum;        // per-lane: sum of e for head (lane&3)
};

__device__ __forceinline__ void token_step(
    AccState& st, const float4 k4, const float4 v4,
    const uint64_t q0lo, const uint64_t q0hi, const uint64_t q1lo, const uint64_t q1hi,
    const uint64_t q2lo, const uint64_t q2hi, const uint64_t q3lo, const uint64_t q3hi,
    const float rel, const float slp_lane, const int lane)
{
    const uint64_t klo = pack2(k4.x, k4.y);
    const uint64_t khi = pack2(k4.z, k4.w);

    float p0, p1, p2, p3;
    { uint64_t t = fma2(q0hi, khi, mul2(q0lo, klo)); float lo, hi; unpack2(lo, hi, t); p0 = lo + hi; }
    { uint64_t t = fma2(q1hi, khi, mul2(q1lo, klo)); float lo, hi; unpack2(lo, hi, t); p1 = lo + hi; }
    { uint64_t t = fma2(q2hi, khi, mul2(q2lo, klo)); float lo, hi; unpack2(lo, hi, t); p2 = lo + hi; }
    { uint64_t t = fma2(q3hi, khi, mul2(q3lo, klo)); float lo, hi; unpack2(lo, hi, t); p3 = lo + hi; }

    const bool b0 = (lane & 1);
    float x01 = b0 ? p1 : p0;
    float y01 = b0 ? p0 : p1;
    x01 += __shfl_xor_sync(FULLMASK, y01, 1);
    float x23 = b0 ? p3 : p2;
    float y23 = b0 ? p2 : p3;
    x23 += __shfl_xor_sync(FULLMASK, y23, 1);
    const bool b1 = (lane & 2);
    float x = b1 ? x23 : x01;
    float y = b1 ? x01 : x23;
    x += __shfl_xor_sync(FULLMASK, y, 2);
    x += __shfl_xor_sync(FULLMASK, x, 4);
    x += __shfl_xor_sync(FULLMASK, x, 8);
    x += __shfl_xor_sync(FULLMASK, x, 16);

    const float e = __expf(fmaf(slp_lane, rel, x));
    st.lsum += e;

    const float e0 = __shfl_sync(FULLMASK, e, 0);
    const float e1 = __shfl_sync(FULLMASK, e, 1);
    const float e2 = __shfl_sync(FULLMASK, e, 2);
    const float e3 = __shfl_sync(FULLMASK, e, 3);

    const uint64_t vlo = pack2(v4.x, v4.y);
    const uint64_t vhi = pack2(v4.z, v4.w);
    const uint64_t e0p = pack2(e0, e0), e1p = pack2(e1, e1);
    const uint64_t e2p = pack2(e2, e2), e3p = pack2(e3, e3);

    st.a0lo = fma2(e0p, vlo, st.a0lo); st.a0hi = fma2(e0p, vhi, st.a0hi);
    st.a1lo = fma2(e1p, vlo, st.a1lo); st.a1hi = fma2(e1p, vhi, st.a1hi);
    st.a2lo = fma2(e2p, vlo, st.a2lo); st.a2hi = fma2(e2p, vhi, st.a2hi);
    st.a3lo = fma2(e3p, vlo, st.a3lo); st.a3hi = fma2(e3p, vhi, st.a3hi);
}

__device__ __forceinline__ void cpa16(uint32_t dst, const void* src) {
    asm volatile("cp.async.cg.shared.global [%0], [%1], 16;" :: "r"(dst), "l"(src));
}
#define CPA_COMMIT() asm volatile("cp.async.commit_group;" ::: "memory")
#define CPA_WAIT(n)  asm volatile("cp.async.wait_group %0;" :: "n"(n) : "memory")

// dynamic smem: kvbuf[3][2][CH][HD]  = 98304 bytes
#define SMEM_BYTES (3 * 2 * CH * HD * 4)
#define KVIDX(buf, kv, t) ((((buf) * 2 + (kv)) * CH + (t)) * HD)

__global__ __launch_bounds__(NTHREADS, 2)
void paged_attn_kernel(const float* __restrict__ q,
                       const float* __restrict__ kcache,
                       const float* __restrict__ vcache,
                       const float* __restrict__ scale_p,
                       const int*   __restrict__ btab,
                       const int*   __restrict__ seqlen,
                       const float* __restrict__ slopes,
                       float*       __restrict__ out)
{
    extern __shared__ float kvf[];     // [3][2][CH][HD]

    const int p    = blockIdx.x % NP;
    const int kv   = (blockIdx.x / NP) % KVH;
    const int s    = blockIdx.x / (NP * KVH);
    const int tid  = threadIdx.x;
    const int lane = tid & 31;
    const int warp = tid >> 5;

    const int len = seqlen[s];
    const int t0  = p * PART;
    if (t0 >= len) return;
    const int tmax = min(PART, len - t0);
    const int np   = (len + PART - 1) / PART;
    const float scale = scale_p[0];

    __shared__ float  wl[NWARPS][GQ];
    __shared__ size_t sbase[PART / BS];    // 16 block row-bases
    __shared__ int    is_last;

    // red[NWARPS][GQ][HD] aliases the first 32 KB of kvf (used outside pipeline)
    float (*red)[GQ][HD] = (float (*)[GQ][HD]) kvf;

    // Stage Q (scaled): 512 values, one per thread
    red[0][0][0 * 0] = red[0][0][0];   // no-op to appease aliasing (removed by compiler)
    (&red[0][0][0])[tid] = q[(s * NUM_HEADS + kv * GQ) * HD + tid] * scale;

    const int nblk = (tmax + BS - 1) >> 4;
    const size_t kvbase   = (size_t)kv * BS * HD;
    const size_t kvstride = (size_t)KVH * BS * HD;
    if (tid < PART / BS) {
        const int idx = min(tid, nblk - 1);
        sbase[tid] = (size_t)btab[s * MAXB + (t0 >> 4) + idx] * kvstride + kvbase;
    }
    __syncthreads();

    const float4 qr0 = ((const float4*)&red[0][0][0])[lane];
    const float4 qr1 = ((const float4*)&red[0][1][0])[lane];
    const float4 qr2 = ((const float4*)&red[0][2][0])[lane];
    const float4 qr3 = ((const float4*)&red[0][3][0])[lane];
    const uint64_t q0lo = pack2(qr0.x, qr0.y), q0hi = pack2(qr0.z, qr0.w);
    const uint64_t q1lo = pack2(qr1.x, qr1.y), q1hi = pack2(qr1.z, qr1.w);
    const uint64_t q2lo = pack2(qr2.x, qr2.y), q2hi = pack2(qr2.z, qr2.w);
    const uint64_t q3lo = pack2(qr3.x, qr3.y), q3hi = pack2(qr3.z, qr3.w);
    __syncthreads();   // Q consumed; kvf free for the pipeline

    const float slp_lane = slopes[kv * GQ + (lane & 3)];
    const float relbase  = (float)(t0 - (len - 1));

    const int nch = (tmax + CH - 1) / CH;

    // chunk = 2 paged blocks: 16 KB K + 16 KB V; 512 threads x 4 x 16 B
    auto copy_chunk = [&](int c, int buf) {
        const int b1 = min(2 * c + 1, nblk - 1);    // clamp (masked in compute)
        const char* ks0 = (const char*)(kcache + sbase[2 * c]) + tid * 16;
        const char* ks1 = (const char*)(kcache + sbase[b1])    + tid * 16;
        const char* vs0 = (const char*)(vcache + sbase[2 * c]) + tid * 16;
        const char* vs1 = (const char*)(vcache + sbase[b1])    + tid * 16;
        uint32_t kdst = (uint32_t)__cvta_generic_to_shared(&kvf[KVIDX(buf, 0, 0)]) + tid * 16;
        uint32_t vdst = (uint32_t)__cvta_generic_to_shared(&kvf[KVIDX(buf, 1, 0)]) + tid * 16;
        cpa16(kdst,        ks0);
        cpa16(kdst + 8192, ks1);
        cpa16(vdst,        vs0);
        cpa16(vdst + 8192, vs1);
    };

    copy_chunk(0, 0); CPA_COMMIT();
    if (nch > 1) { copy_chunk(1, 1); CPA_COMMIT(); }

    AccState st;
    st.a0lo = st.a0hi = st.a1lo = st.a1hi = 0ull;
    st.a2lo = st.a2hi = st.a3lo = st.a3hi = 0ull;
    st.lsum = 0.f;

    for (int c = 0; c < nch; c++) {
        if (c + 1 < nch) { CPA_WAIT(1); } else { CPA_WAIT(0); }
        __syncthreads();   // also retires WAR on buffer (c+2)%3 (consumed at c-1)

        if (c + 2 < nch) { copy_chunk(c + 2, (c + 2) % 3); CPA_COMMIT(); }

        const int b = c % 3;
        const int tl0 = c * CH + warp * 2;      // warp owns 2 adjacent tokens
        const int tl1 = tl0 + 1;
        if (tl0 < tmax) {
            const float4 k4 = ((const float4*)&kvf[KVIDX(b, 0, warp * 2)])[lane];
            const float4 v4 = ((const float4*)&kvf[KVIDX(b, 1, warp * 2)])[lane];
            token_step(st, k4, v4, q0lo, q0hi, q1lo, q1hi, q2lo, q2hi, q3lo, q3hi,
                       relbase + (float)tl0, slp_lane, lane);
        }
        if (tl1 < tmax) {
            const float4 k4 = ((const float4*)&kvf[KVIDX(b, 0, warp * 2 + 1)])[lane];
            const float4 v4 = ((const float4*)&kvf[KVIDX(b, 1, warp * 2 + 1)])[lane];
            token_step(st, k4, v4, q0lo, q0hi, q1lo, q1hi, q2lo, q2hi, q3lo, q3hi,
                       relbase + (float)tl1, slp_lane, lane);
        }
    }
    __syncthreads();   // all compute done before red aliases kvf

    // Unpack accumulators, cross-warp reduce in smem.
    float4 a0, a1, a2, a3;
    unpack2(a0.x, a0.y, st.a0lo); unpack2(a0.z, a0.w, st.a0hi);
    unpack2(a1.x, a1.y, st.a1lo); unpack2(a1.z, a1.w, st.a1hi);
    unpack2(a2.x, a2.y, st.a2lo); unpack2(a2.z, a2.w, st.a2hi);
    unpack2(a3.x, a3.y, st.a3lo); unpack2(a3.z, a3.w, st.a3hi);

    if (lane < GQ) wl[warp][lane] = st.lsum;
    ((float4*)&red[warp][0][0])[lane] = a0;
    ((float4*)&red[warp][1][0])[lane] = a1;
    ((float4*)&red[warp][2][0])[lane] = a2;
    ((float4*)&red[warp][3][0])[lane] = a3;
    __syncthreads();

    // 512 threads = one (head, dim) each
    const int d = tid & 127;
    const int g = tid >> 7;
    float r = 0.f;
    #pragma unroll
    for (int w = 0; w < NWARPS; w++) r += red[w][g][d];

    const int    skv = s * KVH + kv;
    const size_t pb  = ((size_t)skv * NP + p) * GQ;
    g_pacc[(pb + g) * HD + d] = r;
    if (tid < GQ) {
        float L = 0.f;
        #pragma unroll
        for (int w = 0; w < NWARPS; w++) L += wl[w][tid];
        g_pl[pb + tid] = L;
    }

    // ---- Decoupled completion: last CTA for this (s, kv) combines ----
    __threadfence();
    __syncthreads();
    if (tid == 0)
        is_last = (atomicAdd(&g_cnt[skv], 1) == np - 1) ? 1 : 0;
    __syncthreads();
    if (!is_last) return;
    __threadfence();

    const size_t base = (size_t)skv * NP * GQ;
    float L = 0.f, o = 0.f;
    for (int pp = 0; pp < np; pp++) {
        const size_t i = base + (size_t)pp * GQ + g;
        L += g_pl[i];
        o += g_pacc[i * HD + d];
    }
    out[(size_t)(s * NUM_HEADS + kv * GQ + g) * HD + d] = o / L;

    if (tid == 0) g_cnt[skv] = 0;
}

extern "C" void kernel_launch(void* const* d_in, const int* in_sizes, int n_in,
                              void* d_out, int out_size) {
    const float* query       = (const float*)d_in[0];
    const float* key_cache   = (const float*)d_in[1];
    const float* value_cache = (const float*)d_in[2];
    const float* scale       = (const float*)d_in[4];
    const int*   block_tab   = (const int*)  d_in[5];
    const int*   seq_lens    = (const int*)  d_in[6];
    const float* alibi       = (const float*)d_in[9];
    float* out = (float*)d_out;

    cudaFuncSetAttribute(paged_attn_kernel,
                         cudaFuncAttributeMaxDynamicSharedMemorySize, SMEM_BYTES);
    paged_attn_kernel<<<NUM_SEQS * KVH * NP, NTHREADS, SMEM_BYTES>>>(
        query, key_cache, value_cache, scale, block_tab, seq_lens, alibi, out);
}

// round 16
// speedup vs baseline: 1.2017x; 1.2017x over previous
#include <cuda_runtime.h>
#include <math.h>
#include <stdint.h>

#define NUM_SEQS   64
#define NUM_HEADS  32
#define KVH        8
#define GQ         4      // query heads per kv head
#define HD         128    // head size
#define BS         16     // paged block size
#define MAXL       2048
#define MAXB       128    // max blocks per seq
#define PART       128    // tokens per split-KV partition
#define NP         (MAXL / PART)   // 16
#define NCHMAX     (PART / BS)     // 8 chunks (one paged block each)
#define NTHREADS   256
#define NWARPS     8
#define FULLMASK   0xffffffffu

// Split-KV scratch (device globals)
__device__ float g_pacc[NUM_SEQS * KVH * NP * GQ * HD];
__device__ float g_pl[NUM_SEQS * KVH * NP * GQ];
__device__ int   g_cnt[NUM_SEQS * KVH];    // zero-initialized; self-cleaning

struct AccState {
    float4 a0, a1, a2, a3;
    float  lsum;           // per-lane: sum of e for head (lane&3)
};

// One token: dot for 4 heads -> transposed butterfly (lane l ends with the
// COMPLETE score of head l&3) -> single exp/lane -> broadcast -> V FMA.
__device__ __forceinline__ void token_step(
    AccState& st, const float4 k4, const float4 v4,
    const float4 qr0, const float4 qr1, const float4 qr2, const float4 qr3,
    const float rel, const float slp_lane, const int lane)
{
    float p0 = qr0.x*k4.x + qr0.y*k4.y + qr0.z*k4.z + qr0.w*k4.w;
    float p1 = qr1.x*k4.x + qr1.y*k4.y + qr1.z*k4.z + qr1.w*k4.w;
    float p2 = qr2.x*k4.x + qr2.y*k4.y + qr2.z*k4.z + qr2.w*k4.w;
    float p3 = qr3.x*k4.x + qr3.y*k4.y + qr3.z*k4.z + qr3.w*k4.w;

    const bool b0 = (lane & 1);
    float x01 = b0 ? p1 : p0;
    float y01 = b0 ? p0 : p1;
    x01 += __shfl_xor_sync(FULLMASK, y01, 1);
    float x23 = b0 ? p3 : p2;
    float y23 = b0 ? p2 : p3;
    x23 += __shfl_xor_sync(FULLMASK, y23, 1);
    const bool b1 = (lane & 2);
    float x = b1 ? x23 : x01;
    float y = b1 ? x01 : x23;
    x += __shfl_xor_sync(FULLMASK, y, 2);
    x += __shfl_xor_sync(FULLMASK, x, 4);
    x += __shfl_xor_sync(FULLMASK, x, 8);
    x += __shfl_xor_sync(FULLMASK, x, 16);

    const float e = __expf(fmaf(slp_lane, rel, x));
    st.lsum += e;

    const float e0 = __shfl_sync(FULLMASK, e, 0);
    const float e1 = __shfl_sync(FULLMASK, e, 1);
    const float e2 = __shfl_sync(FULLMASK, e, 2);
    const float e3 = __shfl_sync(FULLMASK, e, 3);

    st.a0.x += e0*v4.x; st.a0.y += e0*v4.y; st.a0.z += e0*v4.z; st.a0.w += e0*v4.w;
    st.a1.x += e1*v4.x; st.a1.y += e1*v4.y; st.a1.z += e1*v4.z; st.a1.w += e1*v4.w;
    st.a2.x += e2*v4.x; st.a2.y += e2*v4.y; st.a2.z += e2*v4.z; st.a2.w += e2*v4.w;
    st.a3.x += e3*v4.x; st.a3.y += e3*v4.y; st.a3.z += e3*v4.z; st.a3.w += e3*v4.w;
}

__device__ __forceinline__ void cpa16(uint32_t dst, const void* src) {
    asm volatile("cp.async.cg.shared.global [%0], [%1], 16;" :: "r"(dst), "l"(src));
}
#define CPA_COMMIT() asm volatile("cp.async.commit_group;" ::: "memory")
#define CPA_WAIT(n)  asm volatile("cp.async.wait_group %0;" :: "n"(n) : "memory")

__global__ __launch_bounds__(NTHREADS)
void paged_attn_kernel(const float* __restrict__ q,
                       const float* __restrict__ kcache,
                       const float* __restrict__ vcache,
                       const float* __restrict__ scale_p,
                       const int*   __restrict__ btab,
                       const int*   __restrict__ seqlen,
                       const float* __restrict__ slopes,
                       float*       __restrict__ out)
{
    const int p    = blockIdx.x % NP;
    const int kv   = (blockIdx.x / NP) % KVH;
    const int s    = blockIdx.x / (NP * KVH);
    const int tid  = threadIdx.x;
    const int lane = tid & 31;
    const int warp = tid >> 5;

    const int len = seqlen[s];
    const int t0  = p * PART;
    if (t0 >= len) return;
    const int tmax = min(PART, len - t0);
    const int np   = (len + PART - 1) / PART;
    const float scale = scale_p[0];

    // Warp-private triple buffers: wbuf[warp][buf] = {K0,K1,V0,V1} rows of 128f.
    // 8 warps x 3 bufs x 4 rows x 512 B = 48 KB. First 16 KB aliased as the
    // cross-warp reduction buffer red[NWARPS][GQ][HD] outside the pipeline.
    __shared__ float  wbuf[NWARPS][3][4][HD];
    __shared__ float  wl[NWARPS][GQ];
    __shared__ size_t sbase[NCHMAX];
    __shared__ int    is_last;

    float (*red)[GQ][HD] = (float (*)[GQ][HD]) &wbuf[0][0][0][0];

    // Stage Q (scaled) and block row-bases
    for (int i = tid; i < GQ * HD; i += NTHREADS)
        (&red[0][0][0])[i] = q[(s * NUM_HEADS + kv * GQ) * HD + i] * scale;
    const int nch = (tmax + BS - 1) >> 4;
    if (tid < nch) {
        const size_t kvstride = (size_t)KVH * BS * HD;
        sbase[tid] = (size_t)btab[s * MAXB + (t0 >> 4) + tid] * kvstride
                   + (size_t)kv * BS * HD;
    }
    __syncthreads();

    const float4 qr0 = ((const float4*)&red[0][0][0])[lane];
    const float4 qr1 = ((const float4*)&red[0][1][0])[lane];
    const float4 qr2 = ((const float4*)&red[0][2][0])[lane];
    const float4 qr3 = ((const float4*)&red[0][3][0])[lane];
    __syncthreads();   // Q consumed; wbuf free for pipelines

    const float slp_lane = slopes[kv * GQ + (lane & 3)];
    const float relbase  = (float)(t0 - (len - 1));

    // Per-warp chunk copy: tokens (c*16 + warp*2, +1) are ADJACENT rows in
    // block c -> one 1 KB K range + one 1 KB V range; 2+2 cpa16 per lane.
    // Copy is always in-bounds (block c exists); compute masks invalid tokens.
    auto copy_chunk = [&](int c, int buf) {
        const size_t row = sbase[c] + (size_t)(warp * 2) * HD;
        const char* ksrc = (const char*)(kcache + row) + lane * 16;
        const char* vsrc = (const char*)(vcache + row) + lane * 16;
        uint32_t kdst = (uint32_t)__cvta_generic_to_shared(&wbuf[warp][buf][0][0]) + lane * 16;
        uint32_t vdst = (uint32_t)__cvta_generic_to_shared(&wbuf[warp][buf][2][0]) + lane * 16;
        cpa16(kdst,       ksrc);
        cpa16(kdst + 512, ksrc + 512);
        cpa16(vdst,       vsrc);
        cpa16(vdst + 512, vsrc + 512);
        CPA_COMMIT();
    };

    // Prologue: fill depth-2
    copy_chunk(0, 0);
    if (nch > 1) copy_chunk(1, 1);

    AccState st;
    st.a0 = make_float4(0,0,0,0); st.a1 = make_float4(0,0,0,0);
    st.a2 = make_float4(0,0,0,0); st.a3 = make_float4(0,0,0,0);
    st.lsum = 0.f;

    // Barrier-free main loop: warps run their private pipelines independently.
    for (int c = 0; c < nch; c++) {
        if (c + 1 < nch) { CPA_WAIT(1); } else { CPA_WAIT(0); }

        const int b = c % 3;
        const int tl0 = c * BS + warp * 2;
        const int tl1 = tl0 + 1;
        if (tl0 < tmax) {
            const float4 k4 = ((const float4*)&wbuf[warp][b][0][0])[lane];
            const float4 v4 = ((const float4*)&wbuf[warp][b][2][0])[lane];
            token_step(st, k4, v4, qr0, qr1, qr2, qr3,
                       relbase + (float)tl0, slp_lane, lane);
        }
        if (tl1 < tmax) {
            const float4 k4 = ((const float4*)&wbuf[warp][b][1][0])[lane];
            const float4 v4 = ((const float4*)&wbuf[warp][b][3][0])[lane];
            token_step(st, k4, v4, qr0, qr1, qr2, qr3,
                       relbase + (float)tl1, slp_lane, lane);
        }

        if (c + 2 < nch) copy_chunk(c + 2, (c + 2) % 3);
    }
    __syncthreads();   // all warps done before red aliases wbuf

    // Cross-warp reduction in smem.
    if (lane < GQ) wl[warp][lane] = st.lsum;
    ((float4*)&red[warp][0][0])[lane] = st.a0;
    ((float4*)&red[warp][1][0])[lane] = st.a1;
    ((float4*)&red[warp][2][0])[lane] = st.a2;
    ((float4*)&red[warp][3][0])[lane] = st.a3;
    __syncthreads();

    const int d  = tid & 127;
    const int g0 = tid >> 7;
    float r0 = 0.f, r1 = 0.f;
    #pragma unroll
    for (int w = 0; w < NWARPS; w++) {
        r0 += red[w][g0][d];
        r1 += red[w][g0 + 2][d];
    }

    const int    skv = s * KVH + kv;
    const size_t pb  = ((size_t)skv * NP + p) * GQ;
    g_pacc[(pb + g0)     * HD + d] = r0;
    g_pacc[(pb + g0 + 2) * HD + d] = r1;
    if (tid < GQ) {
        float L = 0.f;
        #pragma unroll
        for (int w = 0; w < NWARPS; w++) L += wl[w][tid];
        g_pl[pb + tid] = L;
    }

    // ---- Decoupled completion: last CTA for this (s, kv) combines ----
    __threadfence();
    __syncthreads();
    if (tid == 0)
        is_last = (atomicAdd(&g_cnt[skv], 1) == np - 1) ? 1 : 0;
    __syncthreads();
    if (!is_last) return;
    __threadfence();

    const size_t base = (size_t)skv * NP * GQ;
    float L0 = 0.f, L1 = 0.f, o0 = 0.f, o1 = 0.f;
    for (int pp = 0; pp < np; pp++) {
        const size_t i0 = base + (size_t)pp * GQ + g0;
        const size_t i1 = i0 + 2;
        L0 += g_pl[i0];
        L1 += g_pl[i1];
        o0 += g_pacc[i0 * HD + d];
        o1 += g_pacc[i1 * HD + d];
    }
    out[(size_t)(s * NUM_HEADS + kv * GQ + g0)     * HD + d] = o0 / L0;
    out[(size_t)(s * NUM_HEADS + kv * GQ + g0 + 2) * HD + d] = o1 / L1;

    if (tid == 0) g_cnt[skv] = 0;
}

extern "C" void kernel_launch(void* const* d_in, const int* in_sizes, int n_in,
                              void* d_out, int out_size) {
    const float* query       = (const float*)d_in[0];
    const float* key_cache   = (const float*)d_in[1];
    const float* value_cache = (const float*)d_in[2];
    const float* scale       = (const float*)d_in[4];
    const int*   block_tab   = (const int*)  d_in[5];
    const int*   seq_lens    = (const int*)  d_in[6];
    const float* alibi       = (const float*)d_in[9];
    float* out = (float*)d_out;

    paged_attn_kernel<<<NUM_SEQS * KVH * NP, NTHREADS>>>(
        query, key_cache, value_cache, scale, block_tab, seq_lens, alibi, out);
}